// round 9
// baseline (speedup 1.0000x reference)
#include <cuda_runtime.h>
#include <cstdint>

// ROI pooling (bilinear, half-pixel centers, clamped to crop).
//   img:  (1, 1024, 1024, 256) float32, NHWC
//   rois: (1, 300, 4) float32 (x0, y0, w, h) -> int
//   out:  (1, 300, 7, 7, 256) float32
//
// R9: persistent CTAs + 2-stage cp.async pipeline. 444 blocks (3/SM, 224 thr)
// loop over the 2100 (roi,px) units; while computing unit u from stage buffer
// cur, the next unit's 28KB of corner rows stream into stage cur^1 via
// cp.async. Removes per-CTA latency exposure + 2100x CTA setup of R1-R8.

#define POOL 7
#define IMG_W 1024
#define CF 256
#define NUNITS (300 * POOL)          // 2100
#define GRID 444                     // 3 blocks per SM (148 SMs)
#define STAGE_FLOATS (POOL * 4 * CF) // 7168 floats = 28KB per stage

__device__ __forceinline__ void cp16(uint32_t d, const float* g) {
    asm volatile("cp.async.cg.shared.global [%0], [%1], 16;" :: "r"(d), "l"(g));
}

// Issue this thread's 4 corner-row chunks (4 x 32B) for unit u into `stage`.
__device__ __forceinline__ void prefetch_unit(
    int u, float* stage, const float* __restrict__ img,
    const float4* __restrict__ rois4, int lane, int py)
{
    const int roi = u / POOL;
    const int px  = u - roi * POOL;
    const float4 rp = __ldg(rois4 + roi);
    const int x0 = (int)rp.x, y0 = (int)rp.y;
    const int w  = (int)rp.z, h  = (int)rp.w;

    float cx = ((float)px + 0.5f) * ((float)w / (float)POOL) - 0.5f;
    cx = fminf(fmaxf(cx, 0.0f), (float)w - 1.0f);
    const int xlo = (int)cx;
    const int xhi = min(xlo + 1, w - 1);

    float cy = ((float)py + 0.5f) * ((float)h / (float)POOL) - 0.5f;
    cy = fminf(fmaxf(cy, 0.0f), (float)h - 1.0f);
    const int ylo = (int)cy;
    const int yhi = min(ylo + 1, h - 1);

    const unsigned rlo = (unsigned)(y0 + ylo) * (IMG_W * CF);
    const unsigned rhi = (unsigned)(y0 + yhi) * (IMG_W * CF);
    const unsigned cL  = (unsigned)(x0 + xlo) * CF;
    const unsigned cR  = (unsigned)(x0 + xhi) * CF;
    const unsigned co  = (unsigned)lane * 8;

    const float* g0 = img + rlo + cL + co;
    const float* g1 = img + rlo + cR + co;
    const float* g2 = img + rhi + cL + co;
    const float* g3 = img + rhi + cR + co;

    float* s = stage + (py * 4) * CF + co;
    const uint32_t d = (uint32_t)__cvta_generic_to_shared(s);
    cp16(d,                 g0); cp16(d + 16,            g0 + 4);
    cp16(d + CF * 4,        g1); cp16(d + CF * 4 + 16,   g1 + 4);
    cp16(d + 2 * CF * 4,    g2); cp16(d + 2 * CF * 4 + 16, g2 + 4);
    cp16(d + 3 * CF * 4,    g3); cp16(d + 3 * CF * 4 + 16, g3 + 4);
}

__device__ __forceinline__ void compute_unit(
    int u, const float* stage, const float4* __restrict__ rois4,
    float* __restrict__ out, int lane, int py)
{
    const int roi = u / POOL;
    const int px  = u - roi * POOL;
    const float4 rp = __ldg(rois4 + roi);
    const int w = (int)rp.z, h = (int)rp.w;

    float cx = ((float)px + 0.5f) * ((float)w / (float)POOL) - 0.5f;
    cx = fminf(fmaxf(cx, 0.0f), (float)w - 1.0f);
    const float fx = cx - (float)(int)cx;

    float cy = ((float)py + 0.5f) * ((float)h / (float)POOL) - 0.5f;
    cy = fminf(fmaxf(cy, 0.0f), (float)h - 1.0f);
    const float fy = cy - (float)(int)cy;

    const float w00 = (1.0f - fy) * (1.0f - fx);
    const float w01 = (1.0f - fy) * fx;
    const float w10 = fy * (1.0f - fx);
    const float w11 = fy * fx;

    const unsigned co = (unsigned)lane * 8;
    const float* s00 = stage + (py * 4 + 0) * CF + co;
    const float* s01 = stage + (py * 4 + 1) * CF + co;
    const float* s10 = stage + (py * 4 + 2) * CF + co;
    const float* s11 = stage + (py * 4 + 3) * CF + co;

    float o[8];
    #pragma unroll
    for (int i = 0; i < 8; i++)
        o[i] = s00[i] * w00 + s01[i] * w01 + s10[i] * w10 + s11[i] * w11;

    float* dst = out + ((unsigned)roi * (POOL * POOL)
                        + (unsigned)(py * POOL + px)) * CF + co;
    const uint64_t* uo = reinterpret_cast<const uint64_t*>(o);
    asm volatile("st.global.v4.b64 [%0], {%1,%2,%3,%4};"
                 :: "l"(dst), "l"(uo[0]), "l"(uo[1]), "l"(uo[2]), "l"(uo[3])
                 : "memory");
}

__global__ void __launch_bounds__(224, 3) roi_pool_kernel(
    const float*  __restrict__ img,
    const float4* __restrict__ rois4,
    float*        __restrict__ out)
{
    extern __shared__ __align__(16) float sbuf[];   // 2 * STAGE_FLOATS

    const int lane = threadIdx.x;   // 0..31
    const int py   = threadIdx.y;   // 0..6

    int u = blockIdx.x;
    int cur = 0;

    if (u < NUNITS)
        prefetch_unit(u, sbuf, img, rois4, lane, py);
    asm volatile("cp.async.commit_group;" ::: "memory");

    for (; u < NUNITS; u += GRID) {
        const int nxt = u + GRID;
        if (nxt < NUNITS)
            prefetch_unit(nxt, sbuf + (cur ^ 1) * STAGE_FLOATS,
                          img, rois4, lane, py);
        asm volatile("cp.async.commit_group;" ::: "memory");
        asm volatile("cp.async.wait_group 1;" ::: "memory");
        __syncthreads();

        compute_unit(u, sbuf + cur * STAGE_FLOATS, rois4, out, lane, py);

        __syncthreads();   // all reads of this stage done before its refill
        cur ^= 1;
    }
}

extern "C" void kernel_launch(void* const* d_in, const int* in_sizes, int n_in,
                              void* d_out, int out_size)
{
    const float*  img   = (const float*)d_in[0];
    const float4* rois4 = (const float4*)d_in[1];
    float* o = (float*)d_out;

    const int smem = 2 * STAGE_FLOATS * sizeof(float);   // 56 KB
    static bool attr_set = false;
    if (!attr_set) {
        cudaFuncSetAttribute(roi_pool_kernel,
                             cudaFuncAttributeMaxDynamicSharedMemorySize, smem);
        attr_set = true;
    }

    dim3 block(32, POOL, 1);    // 224 threads
    roi_pool_kernel<<<GRID, block, smem>>>(img, rois4, o);
}

// round 10
// speedup vs baseline: 1.3851x; 1.3851x over previous
#include <cuda_runtime.h>
#include <cstdint>

// ROI pooling (bilinear, half-pixel centers, clamped to crop).
//   img:  (1, 1024, 1024, 256) float32, NHWC
//   rois: (1, 300, 4) float32 (x0, y0, w, h) -> int
//   out:  (1, 300, 7, 7, 256) float32
//
// R10 = R8 (session best, 10.75us). Nine experiments establish this shape is
// at the traffic roofline (~75MB at ~7TB/s effective):
//  - exact-fit 224-thread blocks, one warp per (pool-row x 1KB channel row)
//  - 32B ld.global.nc.L2::evict_last reads (read set stays L2-resident)
//  - default write-back stores (replay-dirty output lines stay in L2)
//  - 32-bit address math, regs=32, 9 blocks/SM
// Falsified alternatives: MLP8 (neutral), cp.async (neutral), TMA bulk
// (neutral), .cs streaming stores (slightly worse), persistent pipeline
// (-38%).

#define POOL 7
#define IMG_W 1024
#define CF 256          // channels (floats)

struct F8 { float f[8]; };   // 32 bytes

__device__ __forceinline__ F8 ldg_keep32(const float* p) {
    uint64_t u0, u1, u2, u3;
    asm volatile("ld.global.nc.L2::evict_last.v4.b64 {%0,%1,%2,%3}, [%4];"
                 : "=l"(u0), "=l"(u1), "=l"(u2), "=l"(u3) : "l"(p));
    F8 r;
    *reinterpret_cast<uint64_t*>(&r.f[0]) = u0;
    *reinterpret_cast<uint64_t*>(&r.f[2]) = u1;
    *reinterpret_cast<uint64_t*>(&r.f[4]) = u2;
    *reinterpret_cast<uint64_t*>(&r.f[6]) = u3;
    return r;
}

__device__ __forceinline__ void stg32(float* p, const float* v) {
    const uint64_t* u = reinterpret_cast<const uint64_t*>(v);
    asm volatile("st.global.v4.b64 [%0], {%1,%2,%3,%4};"
                 :: "l"(p), "l"(u[0]), "l"(u[1]), "l"(u[2]), "l"(u[3])
                 : "memory");
}

__global__ __launch_bounds__(224) void roi_pool_kernel(
    const float*  __restrict__ img,    // (H*W*256) floats
    const float4* __restrict__ rois4,  // (300) float4 = (x0,y0,w,h)
    float*        __restrict__ out)    // (300*49*256) floats
{
    const int roi = blockIdx.y;
    const int px  = blockIdx.x;      // 0..6
    const int py  = threadIdx.y;     // 0..6 (one warp per pool row)

    const float4 rp = __ldg(rois4 + roi);
    const int x0 = (int)rp.x;
    const int y0 = (int)rp.y;
    const int w  = (int)rp.z;
    const int h  = (int)rp.w;

    // Sample coords, exactly as reference: c = (i+0.5)*(size/P) - 0.5, clamped.
    float cy = ((float)py + 0.5f) * ((float)h / (float)POOL) - 0.5f;
    cy = fminf(fmaxf(cy, 0.0f), (float)h - 1.0f);
    float cx = ((float)px + 0.5f) * ((float)w / (float)POOL) - 0.5f;
    cx = fminf(fmaxf(cx, 0.0f), (float)w - 1.0f);

    const int ylo = (int)cy;
    const int xlo = (int)cx;
    const int yhi = min(ylo + 1, h - 1);
    const int xhi = min(xlo + 1, w - 1);
    const float fy = cy - (float)ylo;
    const float fx = cx - (float)xlo;

    const float w00 = (1.0f - fy) * (1.0f - fx);
    const float w01 = (1.0f - fy) * fx;
    const float w10 = fy * (1.0f - fx);
    const float w11 = fy * fx;

    // Float offsets fit in 32 bits (img = 2^28 floats).
    const unsigned r_lo = (unsigned)(y0 + ylo) * (IMG_W * CF);
    const unsigned r_hi = (unsigned)(y0 + yhi) * (IMG_W * CF);
    const unsigned cL   = (unsigned)(x0 + xlo) * CF;
    const unsigned cR   = (unsigned)(x0 + xhi) * CF;

    const unsigned c8 = (unsigned)threadIdx.x * 8;   // lane * 8 floats (32B)

    const F8 v00 = ldg_keep32(img + r_lo + cL + c8);
    const F8 v01 = ldg_keep32(img + r_lo + cR + c8);
    const F8 v10 = ldg_keep32(img + r_hi + cL + c8);
    const F8 v11 = ldg_keep32(img + r_hi + cR + c8);

    float o[8];
    #pragma unroll
    for (int i = 0; i < 8; i++)
        o[i] = v00.f[i] * w00 + v01.f[i] * w01 + v10.f[i] * w10 + v11.f[i] * w11;

    stg32(out + ((unsigned)roi * (POOL * POOL) + (unsigned)(py * POOL + px)) * CF + c8, o);
}

extern "C" void kernel_launch(void* const* d_in, const int* in_sizes, int n_in,
                              void* d_out, int out_size)
{
    const float*  img   = (const float*)d_in[0];
    const float4* rois4 = (const float4*)d_in[1];
    float* o = (float*)d_out;

    dim3 block(32, POOL, 1);    // 32 lanes x 7 pool rows = 224 (exact fit)
    dim3 grid(POOL, 300, 1);    // px x roi
    roi_pool_kernel<<<grid, block>>>(img, rois4, o);
}